// round 1
// baseline (speedup 1.0000x reference)
#include <cuda_runtime.h>
#include <math.h>
#include <float.h>
#include <stdint.h>

// ---------------- problem constants ----------------
#define BB     4
#define CIN    256
#define HH     200
#define WW     176
#define HWTOT  (HH*WW)          // 35200
#define AA     6
#define NCLS   4
#define NREG   7
#define NOUT   (NCLS*AA + NREG*AA)   // 66 (24 cls + 42 reg)
#define NANCH  (AA*HWTOT)       // 211200
#define KTOP   100

// ---------------- stage-1 tiling ----------------
#define TILE_HW  256
#define CK       16
#define NTHREADS 352            // 11 warps
#define OT       6              // outputs per warp (11*6 = 66)
#define HWT      8              // hw positions per thread (32 lanes * 8 = 256)
#define ESM_STRIDE 67           // padded row stride for epilogue smem
#define WREGION  (TILE_HW*ESM_STRIDE)     // 17152 floats (>= 66*256 = 16896)
#define SMEM_FLOATS (WREGION + CK*TILE_HW)
#define SMEM_BYTES  (SMEM_FLOATS*4)

// ---------------- top-k constants ----------------
#define NBINS   65536
#define CANDMAX 4096

// ---------------- device scratch (static: no allocation allowed) ----------------
__device__ float    g_scores[(size_t)BB*NANCH*NCLS];
__device__ float    g_boxes [(size_t)BB*NANCH*NREG];
__device__ float    g_maxs  [(size_t)BB*NANCH];
__device__ unsigned g_hist  [BB*NBINS];
__device__ int      g_thr   [BB];
__device__ int      g_candCnt[BB];
__device__ float    g_candV [BB*CANDMAX];
__device__ int      g_candI [BB*CANDMAX];

// ============================================================================
// Stage 1: fused 1x1-conv heads (GEMM) + bias + softmax + box decode
// ============================================================================
__global__ __launch_bounds__(NTHREADS)
void head_kernel(const float* __restrict__ x,
                 const float* __restrict__ cls_w, const float* __restrict__ cls_b,
                 const float* __restrict__ reg_w, const float* __restrict__ reg_b,
                 const float* __restrict__ anchors)
{
    extern __shared__ float sm[];
    float* wT  = sm;                 // [256][66] transposed weights (union with esm)
    float* esm = sm;                 // [256][67] epilogue tile (reuses wT region)
    float* xs  = sm + WREGION;       // [CK][256] input chunk

    const int b    = blockIdx.y;
    const int hw0  = blockIdx.x * TILE_HW;
    const int tid  = threadIdx.x;
    const int lane = tid & 31;
    const int wrp  = tid >> 5;       // 0..10
    const int obase = wrp * OT;

    // load combined weights transposed into smem: wT[c*66 + o]
    for (int idx = tid; idx < NOUT*CIN; idx += NTHREADS) {
        int o = idx >> 8;            // /256
        int c = idx & 255;
        float v = (o < NCLS*AA) ? cls_w[o*CIN + c] : reg_w[(o - NCLS*AA)*CIN + c];
        wT[c*NOUT + o] = v;
    }

    float acc[OT][HWT];
    #pragma unroll
    for (int j = 0; j < OT; j++)
        #pragma unroll
        for (int i = 0; i < HWT; i++) acc[j][i] = 0.f;

    const float* xb = x + (size_t)b * CIN * HWTOT;
    const bool interior = (hw0 + TILE_HW <= HWTOT);

    for (int cc = 0; cc < CIN; cc += CK) {
        __syncthreads();   // protects xs reuse; first iter: publishes wT
        if (interior) {
            for (int idx = tid; idx < CK*(TILE_HW/4); idx += NTHREADS) {
                int c  = idx >> 6;          // /(TILE_HW/4)
                int f4 = idx & 63;
                float4 v = *(const float4*)(xb + (size_t)(cc + c)*HWTOT + hw0 + f4*4);
                *(float4*)(xs + c*TILE_HW + f4*4) = v;
            }
        } else {
            for (int idx = tid; idx < CK*TILE_HW; idx += NTHREADS) {
                int c   = idx >> 8;
                int col = idx & 255;
                float v = (hw0 + col < HWTOT) ? xb[(size_t)(cc + c)*HWTOT + hw0 + col] : 0.f;
                xs[c*TILE_HW + col] = v;
            }
        }
        __syncthreads();

        #pragma unroll
        for (int c = 0; c < CK; c++) {
            const float* wrow = &wT[(cc + c)*NOUT + obase];
            float2 w01 = *(const float2*)(wrow + 0);
            float2 w23 = *(const float2*)(wrow + 2);
            float2 w45 = *(const float2*)(wrow + 4);
            float wv[OT] = {w01.x, w01.y, w23.x, w23.y, w45.x, w45.y};
            float xv[HWT];
            #pragma unroll
            for (int i = 0; i < HWT; i++) xv[i] = xs[c*TILE_HW + lane + 32*i];
            #pragma unroll
            for (int j = 0; j < OT; j++)
                #pragma unroll
                for (int i = 0; i < HWT; i++)
                    acc[j][i] = fmaf(wv[j], xv[i], acc[j][i]);
        }
    }

    __syncthreads();   // done reading wT; reuse region as esm

    // add bias, scatter accumulators into epilogue tile esm[hw][o]
    float bias[OT];
    #pragma unroll
    for (int j = 0; j < OT; j++) {
        int o = obase + j;
        bias[j] = (o < NCLS*AA) ? cls_b[o] : reg_b[o - NCLS*AA];
    }
    #pragma unroll
    for (int j = 0; j < OT; j++)
        #pragma unroll
        for (int i = 0; i < HWT; i++)
            esm[(lane + 32*i)*ESM_STRIDE + obase + j] = acc[j][i] + bias[j];
    __syncthreads();

    // per-anchor epilogue: softmax + decode + store
    for (int t = tid; t < TILE_HW*AA; t += NTHREADS) {
        int hwl = t / AA;
        int a   = t - hwl*AA;
        if (hw0 + hwl >= HWTOT) continue;
        int n = (hw0 + hwl)*AA + a;                 // anchor index within batch
        const float* e = esm + hwl*ESM_STRIDE;

        // softmax over 4 class logits (channel o = a*4 + c)
        float l0 = e[a*4+0], l1 = e[a*4+1], l2 = e[a*4+2], l3 = e[a*4+3];
        float m  = fmaxf(fmaxf(l0, l1), fmaxf(l2, l3));
        float e0 = expf(l0 - m), e1 = expf(l1 - m), e2 = expf(l2 - m), e3 = expf(l3 - m);
        float inv = 1.f / (e0 + e1 + e2 + e3);
        float p0 = e0*inv, p1 = e1*inv, p2 = e2*inv, p3 = e3*inv;

        size_t base = (size_t)b*NANCH + n;
        *(float4*)(g_scores + base*4) = make_float4(p0, p1, p2, p3);
        g_maxs[base] = fmaxf(fmaxf(p1, p2), p3);

        // decode (channel o = 24 + a*7 + r)
        const float* d  = e + NCLS*AA + a*NREG;
        const float* an = anchors + (size_t)n*NREG;
        float xa = an[0], ya = an[1], za = an[2];
        float dxa = an[3], dya = an[4], dza = an[5], ra = an[6];
        float diag = sqrtf(dxa*dxa + dya*dya);
        float* ob = g_boxes + base*NREG;
        ob[0] = fmaf(d[0], diag, xa);
        ob[1] = fmaf(d[1], diag, ya);
        ob[2] = fmaf(d[2], dza,  za);
        ob[3] = expf(d[3]) * dxa;
        ob[4] = expf(d[4]) * dya;
        ob[5] = expf(d[5]) * dza;
        ob[6] = d[6] + ra;
    }
}

// ============================================================================
// Top-k pipeline: zero -> histogram -> threshold scan -> compact -> sort+gather
// ============================================================================
__global__ void zero_kernel() {
    int i = blockIdx.x*blockDim.x + threadIdx.x;
    if (i < BB*NBINS) g_hist[i] = 0u;
    if (i < BB) g_candCnt[i] = 0;
}

__global__ void hist_kernel() {
    int b = blockIdx.y;
    int stride = gridDim.x * blockDim.x;
    for (int i = blockIdx.x*blockDim.x + threadIdx.x; i < NANCH; i += stride) {
        unsigned bits = __float_as_uint(g_maxs[(size_t)b*NANCH + i]);
        atomicAdd(&g_hist[b*NBINS + (bits >> 16)], 1u);
    }
}

__global__ void scan_kernel() {
    int b = blockIdx.x;
    __shared__ unsigned csum[256];
    const unsigned* h = g_hist + b*NBINS;
    unsigned s = 0;
    for (int k = 0; k < 256; k++) s += h[threadIdx.x*256 + k];
    csum[threadIdx.x] = s;
    __syncthreads();
    if (threadIdx.x == 0) {
        unsigned cum = 0;
        int chunk = 255;
        for (; chunk >= 0; chunk--) {
            if (cum + csum[chunk] >= (unsigned)KTOP) break;
            cum += csum[chunk];
        }
        if (chunk < 0) chunk = 0;
        int t = chunk*256;
        for (int k = 255; k >= 0; k--) {
            unsigned c = h[chunk*256 + k];
            if (cum + c >= (unsigned)KTOP) { t = chunk*256 + k; break; }
            cum += c;
        }
        g_thr[b] = t;
    }
}

__global__ void compact_kernel() {
    int b = blockIdx.y;
    int thr = g_thr[b];
    int stride = gridDim.x * blockDim.x;
    for (int i = blockIdx.x*blockDim.x + threadIdx.x; i < NANCH; i += stride) {
        float v = g_maxs[(size_t)b*NANCH + i];
        if ((int)(__float_as_uint(v) >> 16) >= thr) {
            int p = atomicAdd(&g_candCnt[b], 1);
            if (p < CANDMAX) {
                g_candV[b*CANDMAX + p] = v;
                g_candI[b*CANDMAX + p] = i;
            }
        }
    }
}

__global__ __launch_bounds__(1024)
void topk_kernel(float* __restrict__ outS, float* __restrict__ outB) {
    int b = blockIdx.x;
    __shared__ float sv[CANDMAX];
    __shared__ int   si[CANDMAX];
    int cnt = g_candCnt[b];
    if (cnt > CANDMAX) cnt = CANDMAX;
    for (int k = threadIdx.x; k < CANDMAX; k += 1024) {
        if (k < cnt) { sv[k] = g_candV[b*CANDMAX + k]; si[k] = g_candI[b*CANDMAX + k]; }
        else         { sv[k] = -FLT_MAX;               si[k] = 0x7FFFFFFF; }
    }
    __syncthreads();
    // bitonic sort, descending by (value, then ascending index) — matches top_k tie-break
    for (int k2 = 2; k2 <= CANDMAX; k2 <<= 1) {
        for (int j = k2 >> 1; j > 0; j >>= 1) {
            for (int i = threadIdx.x; i < CANDMAX; i += 1024) {
                int ixj = i ^ j;
                if (ixj > i) {
                    float va = sv[i], vb = sv[ixj];
                    int   ia = si[i], ib = si[ixj];
                    bool a_below_b = (va < vb) || (va == vb && ia > ib);
                    bool up = ((i & k2) == 0);
                    bool do_swap = up ? a_below_b : !a_below_b;
                    if (do_swap) { sv[i] = vb; sv[ixj] = va; si[i] = ib; si[ixj] = ia; }
                }
            }
            __syncthreads();
        }
    }
    if (threadIdx.x < KTOP) {
        int k = threadIdx.x;
        int n = si[k];
        size_t base = (size_t)b*NANCH + n;
        float4 s4 = *(const float4*)(g_scores + base*4);
        *(float4*)(outS + ((size_t)b*KTOP + k)*4) = s4;
        const float* bx = g_boxes + base*NREG;
        float* ob = outB + ((size_t)b*KTOP + k)*NREG;
        #pragma unroll
        for (int r = 0; r < NREG; r++) ob[r] = bx[r];
    }
}

// ============================================================================
extern "C" void kernel_launch(void* const* d_in, const int* in_sizes, int n_in,
                              void* d_out, int out_size)
{
    const float* x       = (const float*)d_in[0];
    const float* cls_w   = (const float*)d_in[1];
    const float* cls_b   = (const float*)d_in[2];
    const float* reg_w   = (const float*)d_in[3];
    const float* reg_b   = (const float*)d_in[4];
    const float* anchors = (const float*)d_in[5];

    float* outS = (float*)d_out;                 // [B, K, 4]
    float* outB = outS + (size_t)BB*KTOP*NCLS;   // [B, K, 7]

    cudaFuncSetAttribute(head_kernel, cudaFuncAttributeMaxDynamicSharedMemorySize, SMEM_BYTES);

    zero_kernel<<<(BB*NBINS + 255)/256, 256>>>();
    head_kernel<<<dim3((HWTOT + TILE_HW - 1)/TILE_HW, BB), NTHREADS, SMEM_BYTES>>>(
        x, cls_w, cls_b, reg_w, reg_b, anchors);
    hist_kernel<<<dim3(256, BB), 256>>>();
    scan_kernel<<<BB, 256>>>();
    compact_kernel<<<dim3(256, BB), 256>>>();
    topk_kernel<<<BB, 1024>>>(outS, outB);
}

// round 3
// speedup vs baseline: 1.5407x; 1.5407x over previous
#include <cuda_runtime.h>
#include <math.h>
#include <float.h>
#include <stdint.h>

// ---------------- problem constants ----------------
#define BB     4
#define CIN    256
#define HH     200
#define WW     176
#define HWTOT  (HH*WW)          // 35200
#define AA     6
#define NCLS   4
#define NREG   7
#define NOUT   (NCLS*AA + NREG*AA)   // 66 (24 cls + 42 reg)
#define NANCH  (AA*HWTOT)       // 211200
#define KTOP   100

// ---------------- stage-1 tiling ----------------
#define TILE_HW  256
#define CK       16
#define NTHREADS 352            // 11 warps
#define OT       6              // outputs per warp (11*6 = 66)
#define HWT      8              // hw positions per thread (32 lanes * 8 = 256)
#define ESM_STRIDE 67           // padded row stride for epilogue smem
#define WREGION  (TILE_HW*ESM_STRIDE)     // 17152 floats (>= 66*256 = 16896)
#define SMEM_FLOATS (WREGION + CK*TILE_HW)
#define SMEM_BYTES  (SMEM_FLOATS*4)

// ---------------- top-k constants ----------------
#define NBINS   65536
#define CANDMAX 4096

// ---------------- device scratch (static: no allocation allowed) ----------------
__device__ float    g_scores[(size_t)BB*NANCH*NCLS];
__device__ float    g_boxes [(size_t)BB*NANCH*NREG];
__device__ float    g_maxs  [(size_t)BB*NANCH];
__device__ unsigned g_hist  [BB*NBINS];

// ============================================================================
// Stage 0: zero the histogram
// ============================================================================
__global__ void zero_kernel() {
    int i = blockIdx.x*blockDim.x + threadIdx.x;
    if (i < BB*NBINS) g_hist[i] = 0u;
}

// ============================================================================
// Stage 1: fused 1x1-conv heads (GEMM) + bias + softmax + decode + histogram
// ============================================================================
__global__ __launch_bounds__(NTHREADS)
void head_kernel(const float* __restrict__ x,
                 const float* __restrict__ cls_w, const float* __restrict__ cls_b,
                 const float* __restrict__ reg_w, const float* __restrict__ reg_b,
                 const float* __restrict__ anchors)
{
    extern __shared__ float sm[];
    float* wT  = sm;                 // [256][66] transposed weights (union with esm)
    float* esm = sm;                 // [256][67] epilogue tile (reuses wT region)
    float* xs  = sm + WREGION;       // [CK][256] input chunk

    const int b    = blockIdx.y;
    const int hw0  = blockIdx.x * TILE_HW;
    const int tid  = threadIdx.x;
    const int lane = tid & 31;
    const int wrp  = tid >> 5;       // 0..10
    const int obase = wrp * OT;

    // load combined weights transposed into smem: wT[c*66 + o]
    for (int idx = tid; idx < NOUT*CIN; idx += NTHREADS) {
        int o = idx >> 8;            // /256
        int c = idx & 255;
        float v = (o < NCLS*AA) ? cls_w[o*CIN + c] : reg_w[(o - NCLS*AA)*CIN + c];
        wT[c*NOUT + o] = v;
    }

    float acc[OT][HWT];
    #pragma unroll
    for (int j = 0; j < OT; j++)
        #pragma unroll
        for (int i = 0; i < HWT; i++) acc[j][i] = 0.f;

    const float* xb = x + (size_t)b * CIN * HWTOT;
    const bool interior = (hw0 + TILE_HW <= HWTOT);

    for (int cc = 0; cc < CIN; cc += CK) {
        __syncthreads();   // protects xs reuse; first iter: publishes wT
        if (interior) {
            for (int idx = tid; idx < CK*(TILE_HW/4); idx += NTHREADS) {
                int c  = idx >> 6;          // /(TILE_HW/4)
                int f4 = idx & 63;
                float4 v = *(const float4*)(xb + (size_t)(cc + c)*HWTOT + hw0 + f4*4);
                *(float4*)(xs + c*TILE_HW + f4*4) = v;
            }
        } else {
            for (int idx = tid; idx < CK*TILE_HW; idx += NTHREADS) {
                int c   = idx >> 8;
                int col = idx & 255;
                float v = (hw0 + col < HWTOT) ? xb[(size_t)(cc + c)*HWTOT + hw0 + col] : 0.f;
                xs[c*TILE_HW + col] = v;
            }
        }
        __syncthreads();

        #pragma unroll
        for (int c = 0; c < CK; c++) {
            const float* wrow = &wT[(cc + c)*NOUT + obase];
            float2 w01 = *(const float2*)(wrow + 0);
            float2 w23 = *(const float2*)(wrow + 2);
            float2 w45 = *(const float2*)(wrow + 4);
            float wv[OT] = {w01.x, w01.y, w23.x, w23.y, w45.x, w45.y};
            float xv[HWT];
            #pragma unroll
            for (int i = 0; i < HWT; i++) xv[i] = xs[c*TILE_HW + lane + 32*i];
            #pragma unroll
            for (int j = 0; j < OT; j++)
                #pragma unroll
                for (int i = 0; i < HWT; i++)
                    acc[j][i] = fmaf(wv[j], xv[i], acc[j][i]);
        }
    }

    __syncthreads();   // done reading wT; reuse region as esm

    // add bias, scatter accumulators into epilogue tile esm[hw][o]
    float bias[OT];
    #pragma unroll
    for (int j = 0; j < OT; j++) {
        int o = obase + j;
        bias[j] = (o < NCLS*AA) ? cls_b[o] : reg_b[o - NCLS*AA];
    }
    #pragma unroll
    for (int j = 0; j < OT; j++)
        #pragma unroll
        for (int i = 0; i < HWT; i++)
            esm[(lane + 32*i)*ESM_STRIDE + obase + j] = acc[j][i] + bias[j];
    __syncthreads();

    // per-anchor epilogue: softmax + decode + store + warp-aggregated histogram
    for (int t = tid; t < TILE_HW*AA; t += NTHREADS) {
        int hwl = t / AA;
        int a   = t - hwl*AA;
        if (hw0 + hwl >= HWTOT) continue;
        int n = (hw0 + hwl)*AA + a;                 // anchor index within batch
        const float* e = esm + hwl*ESM_STRIDE;

        // softmax over 4 class logits (channel o = a*4 + c)
        float l0 = e[a*4+0], l1 = e[a*4+1], l2 = e[a*4+2], l3 = e[a*4+3];
        float m  = fmaxf(fmaxf(l0, l1), fmaxf(l2, l3));
        float e0 = expf(l0 - m), e1 = expf(l1 - m), e2 = expf(l2 - m), e3 = expf(l3 - m);
        float inv = 1.f / (e0 + e1 + e2 + e3);
        float p0 = e0*inv, p1 = e1*inv, p2 = e2*inv, p3 = e3*inv;

        size_t base = (size_t)b*NANCH + n;
        *(float4*)(g_scores + base*4) = make_float4(p0, p1, p2, p3);
        float mx = fmaxf(fmaxf(p1, p2), p3);
        g_maxs[base] = mx;

        // warp-aggregated histogram update (scores are positive: bits monotonic)
        unsigned bin  = __float_as_uint(mx) >> 16;
        unsigned amask = __activemask();
        unsigned peers = __match_any_sync(amask, bin);
        int leader = __ffs(peers) - 1;
        if ((tid & 31) == leader)
            atomicAdd(&g_hist[b*NBINS + bin], (unsigned)__popc(peers));

        // decode (channel o = 24 + a*7 + r)
        const float* d  = e + NCLS*AA + a*NREG;
        const float* an = anchors + (size_t)n*NREG;
        float xa = an[0], ya = an[1], za = an[2];
        float dxa = an[3], dya = an[4], dza = an[5], ra = an[6];
        float diag = sqrtf(dxa*dxa + dya*dya);
        float* ob = g_boxes + base*NREG;
        ob[0] = fmaf(d[0], diag, xa);
        ob[1] = fmaf(d[1], diag, ya);
        ob[2] = fmaf(d[2], dza,  za);
        ob[3] = expf(d[3]) * dxa;
        ob[4] = expf(d[4]) * dya;
        ob[5] = expf(d[5]) * dza;
        ob[6] = d[6] + ra;
    }
}

// ============================================================================
// Stage 2: per-batch fused threshold-find + compact + sort + gather.
// One block (1024 threads) per batch.
// ============================================================================
__global__ __launch_bounds__(1024)
void select_kernel(float* __restrict__ outS, float* __restrict__ outB)
{
    const int b   = blockIdx.x;
    const int tid = threadIdx.x;
    const int lane = tid & 31;
    const int wrp  = tid >> 5;

    __shared__ unsigned csum[1024];   // per-thread chunk sums (64 bins each)
    __shared__ unsigned wsum[32];     // per-warp sums (2048 bins each)
    __shared__ int      sThr;
    __shared__ int      sCnt;
    __shared__ float    sv[CANDMAX];
    __shared__ int      si[CANDMAX];

    // ---- phase 1: chunk sums of the 65536-bin histogram ----
    const unsigned* h = g_hist + b*NBINS;
    {
        const uint4* h4 = (const uint4*)(h + tid*64);
        unsigned s = 0;
        #pragma unroll
        for (int k = 0; k < 16; k++) {
            uint4 v = h4[k];
            s += v.x + v.y + v.z + v.w;
        }
        csum[tid] = s;
        // warp reduce (contiguous chunk: warp w covers bins [w*2048,(w+1)*2048))
        unsigned ws = s;
        #pragma unroll
        for (int o = 16; o > 0; o >>= 1) ws += __shfl_down_sync(0xFFFFFFFFu, ws, o);
        if (lane == 0) wsum[wrp] = ws;
    }
    if (tid == 0) sCnt = 0;
    __syncthreads();

    // ---- phase 2: hierarchical threshold find (thread 0; ~128 serial steps) ----
    if (tid == 0) {
        unsigned cum = 0;
        int w = 31;
        for (; w > 0; w--) { if (cum + wsum[w] >= (unsigned)KTOP) break; cum += wsum[w]; }
        int t = w*32 + 31;
        for (; t > w*32; t--) { if (cum + csum[t] >= (unsigned)KTOP) break; cum += csum[t]; }
        int thr = t*64;
        for (int k = 63; k >= 0; k--) {
            unsigned c = h[t*64 + k];
            if (cum + c >= (unsigned)KTOP) { thr = t*64 + k; break; }
            cum += c;
        }
        sThr = thr;
    }
    __syncthreads();

    // ---- phase 3: compact candidates (coalesced sweep over g_maxs) ----
    {
        const int thr = sThr;
        const float* mv = g_maxs + (size_t)b*NANCH;
        for (int i = tid; i < NANCH; i += 1024) {
            float v = mv[i];
            if ((int)(__float_as_uint(v) >> 16) >= thr) {
                int p = atomicAdd(&sCnt, 1);
                if (p < CANDMAX) { sv[p] = v; si[p] = i; }
            }
        }
    }
    __syncthreads();

    int cnt = sCnt;
    if (cnt > CANDMAX) cnt = CANDMAX;
    // round up to power of 2 (min 128)
    int p2 = 128;
    while (p2 < cnt) p2 <<= 1;
    for (int k = cnt + tid; k < p2; k += 1024) { sv[k] = -FLT_MAX; si[k] = 0x7FFFFFFF; }
    __syncthreads();

    // ---- phase 4: bitonic sort desc by (value, then ascending index) ----
    for (int k2 = 2; k2 <= p2; k2 <<= 1) {
        for (int j = k2 >> 1; j > 0; j >>= 1) {
            for (int i = tid; i < p2; i += 1024) {
                int ixj = i ^ j;
                if (ixj > i) {
                    float va = sv[i], vb = sv[ixj];
                    int   ia = si[i], ib = si[ixj];
                    bool a_below_b = (va < vb) || (va == vb && ia > ib);
                    bool up = ((i & k2) == 0);
                    if (up ? a_below_b : !a_below_b) {
                        sv[i] = vb; sv[ixj] = va; si[i] = ib; si[ixj] = ia;
                    }
                }
            }
            __syncthreads();
        }
    }

    // ---- phase 5: gather top-K ----
    if (tid < KTOP) {
        int k = tid;
        int n = si[k];
        size_t base = (size_t)b*NANCH + n;
        float4 s4 = *(const float4*)(g_scores + base*4);
        *(float4*)(outS + ((size_t)b*KTOP + k)*4) = s4;
        const float* bx = g_boxes + base*NREG;
        float* ob = outB + ((size_t)b*KTOP + k)*NREG;
        #pragma unroll
        for (int r = 0; r < NREG; r++) ob[r] = bx[r];
    }
}

// ============================================================================
extern "C" void kernel_launch(void* const* d_in, const int* in_sizes, int n_in,
                              void* d_out, int out_size)
{
    const float* x       = (const float*)d_in[0];
    const float* cls_w   = (const float*)d_in[1];
    const float* cls_b   = (const float*)d_in[2];
    const float* reg_w   = (const float*)d_in[3];
    const float* reg_b   = (const float*)d_in[4];
    const float* anchors = (const float*)d_in[5];

    float* outS = (float*)d_out;                 // [B, K, 4]
    float* outB = outS + (size_t)BB*KTOP*NCLS;   // [B, K, 7]

    cudaFuncSetAttribute(head_kernel, cudaFuncAttributeMaxDynamicSharedMemorySize, SMEM_BYTES);

    zero_kernel<<<(BB*NBINS + 255)/256, 256>>>();
    head_kernel<<<dim3((HWTOT + TILE_HW - 1)/TILE_HW, BB), NTHREADS, SMEM_BYTES>>>(
        x, cls_w, cls_b, reg_w, reg_b, anchors);
    select_kernel<<<BB, 1024>>>(outS, outB);
}

// round 4
// speedup vs baseline: 1.7462x; 1.1334x over previous
#include <cuda_runtime.h>
#include <math.h>
#include <float.h>
#include <stdint.h>

// ---------------- problem constants ----------------
#define BB     4
#define CIN    256
#define HH     200
#define WW     176
#define HWTOT  (HH*WW)          // 35200
#define AA     6
#define NCLS   4
#define NREG   7
#define NOUT   (NCLS*AA + NREG*AA)   // 66 (24 cls + 42 reg)
#define NANCH  (AA*HWTOT)       // 211200
#define KTOP   100
#define BOXSTRIDE 8             // padded box row in scratch

// ---------------- stage-1 tiling ----------------
#define TILE_HW  256
#define CK       16
#define NITER    (CIN/CK)       // 16
#define NTHREADS 352            // 11 warps
#define OT       6              // outputs per warp (11*6 = 66)
#define HWT      8              // hw positions per thread (32 lanes * 8 = 256)
#define ESM_STRIDE 67           // padded row stride for epilogue smem
#define WREGION  (TILE_HW*ESM_STRIDE)     // 17152 floats (>= 66*256 = 16896)
#define CHUNK_FLOATS (CK*TILE_HW)         // 4096
#define CHUNK_F4 (CHUNK_FLOATS/4)         // 1024
#define SMEM_FLOATS (WREGION + 2*CHUNK_FLOATS)
#define SMEM_BYTES  (SMEM_FLOATS*4)       // ~101 KB

// ---------------- top-k constants ----------------
#define NBINS   65536
#define CANDMAX 4096

// ---------------- device scratch (static: no allocation allowed) ----------------
__device__ float    g_scores[(size_t)BB*NANCH*NCLS];
__device__ float    g_boxes [(size_t)BB*NANCH*BOXSTRIDE];
__device__ float    g_maxs  [(size_t)BB*NANCH];
__device__ unsigned g_hist  [BB*NBINS];

// ---------------- cp.async helpers ----------------
__device__ __forceinline__ void cp16(uint32_t smem_addr, const void* gptr) {
    asm volatile("cp.async.ca.shared.global [%0], [%1], 16;"
                 :: "r"(smem_addr), "l"(gptr));
}
__device__ __forceinline__ void cp_commit() {
    asm volatile("cp.async.commit_group;");
}
template<int N> __device__ __forceinline__ void cp_wait() {
    asm volatile("cp.async.wait_group %0;" :: "n"(N));
}

// ============================================================================
// Stage 0: zero the histogram
// ============================================================================
__global__ void zero_kernel() {
    int i = blockIdx.x*blockDim.x + threadIdx.x;
    if (i < BB*NBINS/4) ((uint4*)g_hist)[i] = make_uint4(0u,0u,0u,0u);
}

// ============================================================================
// Stage 1: fused 1x1-conv heads (GEMM) + bias + softmax + decode + histogram
// Double-buffered cp.async mainloop.
// ============================================================================
__global__ __launch_bounds__(NTHREADS)
void head_kernel(const float* __restrict__ x,
                 const float* __restrict__ cls_w, const float* __restrict__ cls_b,
                 const float* __restrict__ reg_w, const float* __restrict__ reg_b,
                 const float* __restrict__ anchors)
{
    extern __shared__ float sm[];
    float* wT  = sm;                 // [256][66] transposed weights (union with esm)
    float* esm = sm;                 // [256][67] epilogue tile (reuses wT region)
    float* xsA = sm + WREGION;       // buffer 0: [CK][256]
    float* xsB = xsA + CHUNK_FLOATS; // buffer 1

    const int b    = blockIdx.y;
    const int hw0  = blockIdx.x * TILE_HW;
    const int tid  = threadIdx.x;
    const int lane = tid & 31;
    const int wrp  = tid >> 5;       // 0..10
    const int obase = wrp * OT;

    const float* xb = x + (size_t)b * CIN * HWTOT;
    const uint32_t xsA_s = (uint32_t)__cvta_generic_to_shared(xsA);
    const uint32_t xsB_s = (uint32_t)__cvta_generic_to_shared(xsB);

    // issue async copy of chunk cc into a buffer
    auto issue_chunk = [&](int cc, float* dst, uint32_t dst_s) {
        for (int idx = tid; idx < CHUNK_F4; idx += NTHREADS) {
            int c   = idx >> 6;          // /64
            int f4  = idx & 63;
            int col = f4 * 4;
            if (hw0 + col < HWTOT) {
                cp16(dst_s + (uint32_t)(c*TILE_HW + col)*4,
                     xb + (size_t)(cc + c)*HWTOT + hw0 + col);
            } else {
                *(float4*)(dst + c*TILE_HW + col) = make_float4(0.f,0.f,0.f,0.f);
            }
        }
        cp_commit();
    };

    // prefetch chunk 0 into buffer A
    issue_chunk(0, xsA, xsA_s);

    // load combined weights transposed into smem: wT[c*66 + o]
    for (int idx = tid; idx < NOUT*CIN; idx += NTHREADS) {
        int o = idx >> 8;            // /256
        int c = idx & 255;
        float v = (o < NCLS*AA) ? cls_w[o*CIN + c] : reg_w[(o - NCLS*AA)*CIN + c];
        wT[c*NOUT + o] = v;
    }

    float acc[OT][HWT];
    #pragma unroll
    for (int j = 0; j < OT; j++)
        #pragma unroll
        for (int i = 0; i < HWT; i++) acc[j][i] = 0.f;

    #pragma unroll 1
    for (int it = 0; it < NITER; it++) {
        const int cc = it * CK;
        float* cur = (it & 1) ? xsB : xsA;
        if (it + 1 < NITER) {
            if (it > 0) __syncthreads();   // everyone done computing on the other buffer
            float*   nxt   = (it & 1) ? xsA : xsB;
            uint32_t nxt_s = (it & 1) ? xsA_s : xsB_s;
            issue_chunk(cc + CK, nxt, nxt_s);
            cp_wait<1>();                  // current chunk complete
        } else {
            cp_wait<0>();
        }
        __syncthreads();                   // cp.async data + wT (first iter) visible

        #pragma unroll
        for (int c = 0; c < CK; c++) {
            const float* wrow = &wT[(cc + c)*NOUT + obase];
            float2 w01 = *(const float2*)(wrow + 0);
            float2 w23 = *(const float2*)(wrow + 2);
            float2 w45 = *(const float2*)(wrow + 4);
            float wv[OT] = {w01.x, w01.y, w23.x, w23.y, w45.x, w45.y};
            float xv[HWT];
            #pragma unroll
            for (int i = 0; i < HWT; i++) xv[i] = cur[c*TILE_HW + lane + 32*i];
            #pragma unroll
            for (int j = 0; j < OT; j++)
                #pragma unroll
                for (int i = 0; i < HWT; i++)
                    acc[j][i] = fmaf(wv[j], xv[i], acc[j][i]);
        }
    }

    __syncthreads();   // done reading wT; reuse region as esm

    // add bias, scatter accumulators into epilogue tile esm[hw][o]
    float bias[OT];
    #pragma unroll
    for (int j = 0; j < OT; j++) {
        int o = obase + j;
        bias[j] = (o < NCLS*AA) ? cls_b[o] : reg_b[o - NCLS*AA];
    }
    #pragma unroll
    for (int j = 0; j < OT; j++)
        #pragma unroll
        for (int i = 0; i < HWT; i++)
            esm[(lane + 32*i)*ESM_STRIDE + obase + j] = acc[j][i] + bias[j];
    __syncthreads();

    // per-anchor epilogue: softmax + decode + store + warp-aggregated histogram
    for (int t = tid; t < TILE_HW*AA; t += NTHREADS) {
        int hwl = t / AA;
        int a   = t - hwl*AA;
        if (hw0 + hwl >= HWTOT) continue;
        int n = (hw0 + hwl)*AA + a;                 // anchor index within batch
        const float* e = esm + hwl*ESM_STRIDE;

        // softmax over 4 class logits (channel o = a*4 + c)
        float l0 = e[a*4+0], l1 = e[a*4+1], l2 = e[a*4+2], l3 = e[a*4+3];
        float m  = fmaxf(fmaxf(l0, l1), fmaxf(l2, l3));
        float e0 = expf(l0 - m), e1 = expf(l1 - m), e2 = expf(l2 - m), e3 = expf(l3 - m);
        float inv = 1.f / (e0 + e1 + e2 + e3);
        float p0 = e0*inv, p1 = e1*inv, p2 = e2*inv, p3 = e3*inv;

        size_t base = (size_t)b*NANCH + n;
        *(float4*)(g_scores + base*4) = make_float4(p0, p1, p2, p3);
        float mx = fmaxf(fmaxf(p1, p2), p3);
        g_maxs[base] = mx;

        // warp-aggregated histogram update (scores are positive: bits monotonic)
        unsigned bin  = __float_as_uint(mx) >> 16;
        unsigned amask = __activemask();
        unsigned peers = __match_any_sync(amask, bin);
        int leader = __ffs(peers) - 1;
        if ((tid & 31) == leader)
            atomicAdd(&g_hist[b*NBINS + bin], (unsigned)__popc(peers));

        // decode (channel o = 24 + a*7 + r); padded stride-8 vector stores
        const float* d  = e + NCLS*AA + a*NREG;
        const float* an = anchors + (size_t)n*NREG;
        float xa = an[0], ya = an[1], za = an[2];
        float dxa = an[3], dya = an[4], dza = an[5], ra = an[6];
        float diag = sqrtf(dxa*dxa + dya*dya);
        float* ob = g_boxes + base*BOXSTRIDE;
        float4 b0, b1;
        b0.x = fmaf(d[0], diag, xa);
        b0.y = fmaf(d[1], diag, ya);
        b0.z = fmaf(d[2], dza,  za);
        b0.w = expf(d[3]) * dxa;
        b1.x = expf(d[4]) * dya;
        b1.y = expf(d[5]) * dza;
        b1.z = d[6] + ra;
        b1.w = 0.f;
        *(float4*)(ob + 0) = b0;
        *(float4*)(ob + 4) = b1;
    }
}

// ============================================================================
// Stage 2: per-batch fused threshold-find + compact + sort + gather.
// One block (1024 threads) per batch.
// ============================================================================
__global__ __launch_bounds__(1024)
void select_kernel(float* __restrict__ outS, float* __restrict__ outB)
{
    const int b   = blockIdx.x;
    const int tid = threadIdx.x;
    const int lane = tid & 31;
    const int wrp  = tid >> 5;

    __shared__ unsigned csum[1024];   // per-thread chunk sums (64 bins each)
    __shared__ unsigned wsum[32];     // per-warp sums (2048 bins each)
    __shared__ int      sThr;
    __shared__ int      sCnt;
    __shared__ float    sv[CANDMAX];
    __shared__ int      si[CANDMAX];

    // ---- phase 1: chunk sums of the 65536-bin histogram ----
    const unsigned* h = g_hist + b*NBINS;
    {
        const uint4* h4 = (const uint4*)(h + tid*64);
        unsigned s = 0;
        #pragma unroll
        for (int k = 0; k < 16; k++) {
            uint4 v = h4[k];
            s += v.x + v.y + v.z + v.w;
        }
        csum[tid] = s;
        unsigned ws = s;
        #pragma unroll
        for (int o = 16; o > 0; o >>= 1) ws += __shfl_down_sync(0xFFFFFFFFu, ws, o);
        if (lane == 0) wsum[wrp] = ws;
    }
    if (tid == 0) sCnt = 0;
    __syncthreads();

    // ---- phase 2: hierarchical threshold find (thread 0; ~128 serial steps) ----
    if (tid == 0) {
        unsigned cum = 0;
        int w = 31;
        for (; w > 0; w--) { if (cum + wsum[w] >= (unsigned)KTOP) break; cum += wsum[w]; }
        int t = w*32 + 31;
        for (; t > w*32; t--) { if (cum + csum[t] >= (unsigned)KTOP) break; cum += csum[t]; }
        int thr = t*64;
        for (int k = 63; k >= 0; k--) {
            unsigned c = h[t*64 + k];
            if (cum + c >= (unsigned)KTOP) { thr = t*64 + k; break; }
            cum += c;
        }
        sThr = thr;
    }
    __syncthreads();

    // ---- phase 3: compact candidates (coalesced sweep over g_maxs) ----
    {
        const int thr = sThr;
        const float* mv = g_maxs + (size_t)b*NANCH;
        for (int i = tid; i < NANCH; i += 1024) {
            float v = mv[i];
            if ((int)(__float_as_uint(v) >> 16) >= thr) {
                int p = atomicAdd(&sCnt, 1);
                if (p < CANDMAX) { sv[p] = v; si[p] = i; }
            }
        }
    }
    __syncthreads();

    int cnt = sCnt;
    if (cnt > CANDMAX) cnt = CANDMAX;
    int p2 = 128;
    while (p2 < cnt) p2 <<= 1;
    for (int k = cnt + tid; k < p2; k += 1024) { sv[k] = -FLT_MAX; si[k] = 0x7FFFFFFF; }
    __syncthreads();

    // ---- phase 4: bitonic sort desc by (value, then ascending index) ----
    for (int k2 = 2; k2 <= p2; k2 <<= 1) {
        for (int j = k2 >> 1; j > 0; j >>= 1) {
            for (int i = tid; i < p2; i += 1024) {
                int ixj = i ^ j;
                if (ixj > i) {
                    float va = sv[i], vb = sv[ixj];
                    int   ia = si[i], ib = si[ixj];
                    bool a_below_b = (va < vb) || (va == vb && ia > ib);
                    bool up = ((i & k2) == 0);
                    if (up ? a_below_b : !a_below_b) {
                        sv[i] = vb; sv[ixj] = va; si[i] = ib; si[ixj] = ia;
                    }
                }
            }
            __syncthreads();
        }
    }

    // ---- phase 5: gather top-K ----
    if (tid < KTOP) {
        int k = tid;
        int n = si[k];
        size_t base = (size_t)b*NANCH + n;
        float4 s4 = *(const float4*)(g_scores + base*4);
        *(float4*)(outS + ((size_t)b*KTOP + k)*4) = s4;
        const float* bx = g_boxes + base*BOXSTRIDE;
        float4 b0 = *(const float4*)(bx + 0);
        float4 b1 = *(const float4*)(bx + 4);
        float* ob = outB + ((size_t)b*KTOP + k)*NREG;
        ob[0] = b0.x; ob[1] = b0.y; ob[2] = b0.z; ob[3] = b0.w;
        ob[4] = b1.x; ob[5] = b1.y; ob[6] = b1.z;
    }
}

// ============================================================================
extern "C" void kernel_launch(void* const* d_in, const int* in_sizes, int n_in,
                              void* d_out, int out_size)
{
    const float* x       = (const float*)d_in[0];
    const float* cls_w   = (const float*)d_in[1];
    const float* cls_b   = (const float*)d_in[2];
    const float* reg_w   = (const float*)d_in[3];
    const float* reg_b   = (const float*)d_in[4];
    const float* anchors = (const float*)d_in[5];

    float* outS = (float*)d_out;                 // [B, K, 4]
    float* outB = outS + (size_t)BB*KTOP*NCLS;   // [B, K, 7]

    cudaFuncSetAttribute(head_kernel, cudaFuncAttributeMaxDynamicSharedMemorySize, SMEM_BYTES);

    zero_kernel<<<(BB*NBINS/4 + 255)/256, 256>>>();
    head_kernel<<<dim3((HWTOT + TILE_HW - 1)/TILE_HW, BB), NTHREADS, SMEM_BYTES>>>(
        x, cls_w, cls_b, reg_w, reg_b, anchors);
    select_kernel<<<BB, 1024>>>(outS, outB);
}